// round 16
// baseline (speedup 1.0000x reference)
#include <cuda_runtime.h>
#include <math.h>

// ---------------- problem constants ----------------
#define BW_   512              // total windows
#define NW_   64               // mask batch
#define N_    343              // tokens per window
#define NROWS 344              // smem rows actually stored
#define PSW   344              // ps / bm row stride (mult of 4)
#define DIM_  96
#define HEADS 3
#define HD    32
#define NN_   (N_ * N_)        // 117649
#define ROWS_TOT (BW_ * N_)    // 175616

// smem float offsets for attn (ks stride 33, vs stride 32, qs stride 33, ps 64x344)
#define KS_OFF 0
#define VS_OFF (NROWS * 33)
#define QS_OFF (NROWS * 33 + NROWS * 32)
#define PS_OFF (2 * NROWS * 33 + NROWS * 32)
#define SM_FLOATS (PS_OFF + 64 * PSW)      // 55728 floats = 222912 B

// ---------------- f32x2 packed helpers (sm_103a) — used in GEMMs only ----------------
__device__ __forceinline__ unsigned long long f2pack(float lo, float hi) {
    unsigned long long r;
    asm("mov.b64 %0, {%1, %2};" : "=l"(r) : "f"(lo), "f"(hi));
    return r;
}
__device__ __forceinline__ void f2unpack(float& lo, float& hi, unsigned long long v) {
    asm("mov.b64 {%0, %1}, %2;" : "=f"(lo), "=f"(hi) : "l"(v));
}
__device__ __forceinline__ void f2fma(unsigned long long& d, unsigned long long a,
                                      unsigned long long b) {
    asm("fma.rn.f32x2 %0, %1, %2, %3;" : "=l"(d) : "l"(a), "l"(b), "l"(d));
}

// ---------------- device scratch ----------------
__device__ float g_q [BW_ * HEADS * N_ * HD];
__device__ float g_k [BW_ * HEADS * N_ * HD];
__device__ float g_v [BW_ * HEADS * N_ * HD];
__device__ float g_ao[ROWS_TOT * DIM_];
__device__ float g_bm[(size_t)NW_ * HEADS * N_ * PSW];   // bias+mask, padded rows

// ---------------- kernel 1: combined bias+mask table ----------------
__global__ void bm_kernel(const int* __restrict__ rpi, const float* __restrict__ table,
                          const float* __restrict__ mask) {
    size_t idx = (size_t)blockIdx.x * blockDim.x + threadIdx.x;
    const size_t total = (size_t)NW_ * HEADS * N_ * PSW;
    if (idx >= total) return;
    int j  = (int)(idx % PSW);
    size_t rest = idx / PSW;
    int i  = (int)(rest % N_);
    int wh = (int)(rest / N_);
    int h  = wh % HEADS;
    int w  = wh / HEADS;
    float v = 0.0f;
    if (j < N_)
        v = table[rpi[i * N_ + j] * HEADS + h] + mask[((size_t)w * N_ + i) * N_ + j];
    g_bm[idx] = v;
}

// ---------------- GEMM core (k-major smem, packed f32x2 inner loop) ----------------
__device__ __forceinline__ void gemm_core(const float* __restrict__ xg4,   // 128x96 tile
                                          const float* __restrict__ wg4,   // 96x96 slice
                                          float* xs_t, float* ws_t,
                                          float acc[8][6], int tid) {
    {
        const float4* xg = (const float4*)xg4;
        for (int i = tid; i < 128 * 24; i += 256) {
            int r = i / 24, c4 = i % 24;
            float4 v = xg[r * 24 + c4];
            xs_t[(c4 * 4 + 0) * 132 + r] = v.x;
            xs_t[(c4 * 4 + 1) * 132 + r] = v.y;
            xs_t[(c4 * 4 + 2) * 132 + r] = v.z;
            xs_t[(c4 * 4 + 3) * 132 + r] = v.w;
        }
    }
    {
        const float4* wg = (const float4*)wg4;
        for (int i = tid; i < 96 * 24; i += 256) {
            int r = i / 24, c4 = i % 24;
            float4 v = wg[r * 24 + c4];
            ws_t[(c4 * 4 + 0) * 100 + r] = v.x;
            ws_t[(c4 * 4 + 1) * 100 + r] = v.y;
            ws_t[(c4 * 4 + 2) * 100 + r] = v.z;
            ws_t[(c4 * 4 + 3) * 100 + r] = v.w;
        }
    }
    __syncthreads();

    const int tx = tid & 15, ty = tid >> 4;
    unsigned long long acc2[4][6];
#pragma unroll
    for (int i = 0; i < 4; i++)
#pragma unroll
        for (int j = 0; j < 6; j++) acc2[i][j] = 0ull;

#pragma unroll 4
    for (int k = 0; k < 96; k++) {
        float4 a0 = *(const float4*)&xs_t[k * 132 + ty * 8];
        float4 a1 = *(const float4*)&xs_t[k * 132 + ty * 8 + 4];
        float2 b0 = *(const float2*)&ws_t[k * 100 + tx * 6];
        float2 b1 = *(const float2*)&ws_t[k * 100 + tx * 6 + 2];
        float2 b2 = *(const float2*)&ws_t[k * 100 + tx * 6 + 4];
        unsigned long long ap[4];
        ap[0] = f2pack(a0.x, a0.y); ap[1] = f2pack(a0.z, a0.w);
        ap[2] = f2pack(a1.x, a1.y); ap[3] = f2pack(a1.z, a1.w);
        unsigned long long bb[6];
        bb[0] = f2pack(b0.x, b0.x); bb[1] = f2pack(b0.y, b0.y);
        bb[2] = f2pack(b1.x, b1.x); bb[3] = f2pack(b1.y, b1.y);
        bb[4] = f2pack(b2.x, b2.x); bb[5] = f2pack(b2.y, b2.y);
#pragma unroll
        for (int i = 0; i < 4; i++)
#pragma unroll
            for (int j = 0; j < 6; j++) f2fma(acc2[i][j], ap[i], bb[j]);
    }
#pragma unroll
    for (int i = 0; i < 4; i++)
#pragma unroll
        for (int j = 0; j < 6; j++) f2unpack(acc[2 * i][j], acc[2 * i + 1][j], acc2[i][j]);
}

// ---------------- kernel 2: QKV GEMM ----------------
__global__ __launch_bounds__(256, 2) void qkv_gemm(const float* __restrict__ x,
                                                   const float* __restrict__ W,
                                                   const float* __restrict__ bias) {
    extern __shared__ float sm[];
    float* xs_t = sm;
    float* ws_t = sm + 96 * 132;
    const int tid   = threadIdx.x;
    const int which = blockIdx.y;
    const int m0    = blockIdx.x * 128;

    float acc[8][6];
    gemm_core(x + (size_t)m0 * 96, W + (size_t)which * 96 * 96, xs_t, ws_t, acc, tid);

    const int tx = tid & 15, ty = tid >> 4;
    float* base = (which == 0) ? g_q : (which == 1) ? g_k : g_v;
#pragma unroll
    for (int i = 0; i < 8; i++) {
        int m = m0 + ty * 8 + i;
        int bw = m / N_, n = m - bw * N_;
#pragma unroll
        for (int j = 0; j < 6; j++) {
            int c = tx * 6 + j;
            int h = c >> 5, d = c & 31;
            base[(((size_t)bw * HEADS + h) * N_ + n) * HD + d] = acc[i][j] + bias[which * 96 + c];
        }
    }
}

// ---------------- cp.async helpers ----------------
__device__ __forceinline__ void cp_async16(float* smem_dst, const float* gmem_src) {
    unsigned saddr = (unsigned)__cvta_generic_to_shared(smem_dst);
    asm volatile("cp.async.cg.shared.global [%0], [%1], 16;\n" :: "r"(saddr), "l"(gmem_src));
}
__device__ __forceinline__ void cp_async_commit() {
    asm volatile("cp.async.commit_group;\n" ::: "memory");
}
__device__ __forceinline__ void cp_async_wait0() {
    asm volatile("cp.async.wait_group 0;\n" ::: "memory");
}

// prefetch bm rows for tile i0 into warp-owned ps rows (base ty*4). 86 float4/row.
template<int RPW>
__device__ __forceinline__ void prefetch_bm(int i0, float* ps,
                                            const float* __restrict__ bmb,
                                            int ty, int tx) {
#pragma unroll
    for (int rr = 0; rr < RPW; rr++) {
        int i = i0 + ty * RPW + rr;
        if (i > N_ - 1) i = N_ - 1;                 // clamped rows (discarded later)
        const float* src = bmb + (size_t)i * PSW;
        float* dst = ps + (ty * 4 + rr) * PSW;
        cp_async16(dst + tx * 4,        src + tx * 4);
        cp_async16(dst + (tx + 32) * 4, src + (tx + 32) * 4);
        if (tx < 22)
            cp_async16(dst + (tx + 64) * 4, src + (tx + 64) * 4);
    }
    cp_async_commit();
}

// ---------------- softmax + Phase B for one 64-row sub-tile (RPW rows/warp) ----------------
// ps row ownership is warp-constant: warp ty ALWAYS uses ps rows [ty*4, ty*4+RPW).
template<int RPW>
__device__ __forceinline__ void softmax_pb(float (*acc)[11], int i0, float* sm,
                                           int b, int h, int ty, int tx, float scl) {
    float* vs = sm + VS_OFF;
    float* ps = sm + PS_OFF;

    float mx[RPW], sum[RPW];
    // pass 1: add bias+mask, per-lane max
#pragma unroll
    for (int rr = 0; rr < RPW; rr++) {
        const float* bmrow = ps + (ty * 4 + rr) * PSW;
        mx[rr] = -1e30f;
#pragma unroll
        for (int t = 0; t < 11; t++) {
            int j = tx + 32 * t;
            float s = (j < N_) ? fmaf(acc[rr][t], scl, bmrow[j]) : -1e30f;
            acc[rr][t] = s;
            mx[rr] = fmaxf(mx[rr], s);
        }
    }
    // interleaved max reduction (RPW independent shuffle chains)
#pragma unroll
    for (int o = 16; o; o >>= 1)
#pragma unroll
        for (int rr = 0; rr < RPW; rr++)
            mx[rr] = fmaxf(mx[rr], __shfl_xor_sync(0xffffffffu, mx[rr], o));
    // pass 2: exp + per-lane sum
#pragma unroll
    for (int rr = 0; rr < RPW; rr++) {
        sum[rr] = 0.0f;
#pragma unroll
        for (int t = 0; t < 11; t++) {
            int j = tx + 32 * t;
            float e = (j < N_) ? __expf(acc[rr][t] - mx[rr]) : 0.0f;
            acc[rr][t] = e;
            sum[rr] += e;
        }
    }
    // interleaved sum reduction
#pragma unroll
    for (int o = 16; o; o >>= 1)
#pragma unroll
        for (int rr = 0; rr < RPW; rr++)
            sum[rr] += __shfl_xor_sync(0xffffffffu, sum[rr], o);
    // write p (overwrite bm)
#pragma unroll
    for (int rr = 0; rr < RPW; rr++) {
        float inv = 1.0f / sum[rr];
#pragma unroll
        for (int t = 0; t < 11; t++) {
            int j = tx + 32 * t;
            if (j < PSW)
                ps[(ty * 4 + rr) * PSW + j] = acc[rr][t] * inv;
        }
    }
    __syncwarp();

    // ---- Phase B: O = P V (lane = output dim) ----
    float o[RPW];
#pragma unroll
    for (int rr = 0; rr < RPW; rr++) o[rr] = 0.0f;

#pragma unroll 2
    for (int j0 = 0; j0 < PSW; j0 += 4) {
        float pa[RPW][4];
#pragma unroll
        for (int rr = 0; rr < RPW; rr++) {
            float4 p4 = *(const float4*)&ps[(ty * 4 + rr) * PSW + j0];  // broadcast
            pa[rr][0] = p4.x; pa[rr][1] = p4.y; pa[rr][2] = p4.z; pa[rr][3] = p4.w;
        }
#pragma unroll
        for (int jj = 0; jj < 4; jj++) {
            float vv = vs[(j0 + jj) * 32 + tx];
#pragma unroll
            for (int rr = 0; rr < RPW; rr++)
                o[rr] = fmaf(pa[rr][jj], vv, o[rr]);
        }
    }
#pragma unroll
    for (int rr = 0; rr < RPW; rr++) {
        int i = i0 + ty * RPW + rr;
        if (i < N_)
            g_ao[((size_t)b * N_ + i) * DIM_ + h * HD + tx] = o[rr];
    }
    __syncwarp();
}

// ---------------- fused-pair worker: Phase A for TWO sub-tiles with ONE k-stream ----------------
// Sub-tile A always RPW=4 (64 rows); sub-tile B RPW=RB (4 or 2).
// Scalar-d Phase A: ks/qs stride 33 (conflict-free for scalar full-width loads).
template<int RB>
__device__ __forceinline__ void attn_pair(int iA, int iB, float* sm,
                                          const float* __restrict__ bmb,
                                          float scl, int b, int h, int ty, int tx) {
    float* ks = sm + KS_OFF;
    float* qs = sm + QS_OFF;
    float* ps = sm + PS_OFF;

    float accA[4][11], accB[RB][11];
#pragma unroll
    for (int rr = 0; rr < 4; rr++)
#pragma unroll
        for (int t = 0; t < 11; t++) accA[rr][t] = 0.0f;
#pragma unroll
    for (int rr = 0; rr < RB; rr++)
#pragma unroll
        for (int t = 0; t < 11; t++) accB[rr][t] = 0.0f;

    const int qbA = (iA + ty * 4) * 33;
    const int qbB = (iB + ty * RB) * 33;   // rows >= NROWS read in-bounds junk; masked via i<N_ at output
    const int kb  = tx * 33;

#pragma unroll 4
    for (int d = 0; d < 32; d++) {
        float qvA[4], qvB[RB];
#pragma unroll
        for (int rr = 0; rr < 4; rr++)  qvA[rr] = qs[qbA + rr * 33 + d];   // broadcast
#pragma unroll
        for (int rr = 0; rr < RB; rr++) qvB[rr] = qs[qbB + rr * 33 + d];
#pragma unroll
        for (int t = 0; t < 11; t++) {
            float kv = ks[kb + t * 1056 + d];        // j = tx+32t; rows>=NROWS: in-bounds junk
#pragma unroll
            for (int rr = 0; rr < 4; rr++)  accA[rr][t] = fmaf(qvA[rr], kv, accA[rr][t]);
#pragma unroll
            for (int rr = 0; rr < RB; rr++) accB[rr][t] = fmaf(qvB[rr], kv, accB[rr][t]);
        }
    }

    // sub-tile A: bm(A) was prefetched earlier (hidden under Phase A)
    cp_async_wait0();
    __syncwarp();
    softmax_pb<4>(accA, iA, sm, b, h, ty, tx, scl);

    // sub-tile B: prefetch now (ps rows just freed by Phase B of A; warp-private)
    prefetch_bm<RB>(iB, ps, bmb, ty, tx);
    cp_async_wait0();
    __syncwarp();
    softmax_pb<RB>(accB, iB, sm, b, h, ty, tx, scl);
}

// ---------------- kernel 3: attention (512 threads = 16 warps = 4/SMSP) ----------------
// smem: ks [344][33], vs [344][32], qs [344][33], ps [64][344] = 222912 B
__global__ __launch_bounds__(512) void attn_kernel(const float* __restrict__ logit_scale) {
    extern __shared__ float sm[];
    float* ks = sm + KS_OFF;
    float* vs = sm + VS_OFF;
    float* qs = sm + QS_OFF;
    float* ps = sm + PS_OFF;

    const int bx = blockIdx.x;
    const int b  = bx / HEADS;
    const int h  = bx - b * HEADS;
    const int w  = b & (NW_ - 1);
    const int tid = threadIdx.x;
    const int ty = tid >> 5, tx = tid & 31;   // ty: 0..15

    const size_t bh = (size_t)b * HEADS + h;
    const float* qg = g_q + bh * N_ * HD;
    const float* kg = g_k + bh * N_ * HD;
    const float* vg = g_v + bh * N_ * HD;

    const float* bmb = g_bm + ((size_t)w * HEADS + h) * N_ * PSW;

    // tile-0 bm prefetch overlaps staging (ps untouched by staging; warp-private rows)
    prefetch_bm<4>(0, ps, bmb, ty, tx);

    // stage rows 0..343 (row 343 zero-filled), fused q/k L2 normalization
    for (int r = ty; r < NROWS; r += 16) {
        float qv = 0.f, kv = 0.f, vv = 0.f;
        if (r < N_) {
            int off = r * HD + tx;
            qv = qg[off]; kv = kg[off]; vv = vg[off];
        }
        float qss = qv * qv, kss = kv * kv;
#pragma unroll
        for (int o = 16; o; o >>= 1) {
            qss += __shfl_xor_sync(0xffffffffu, qss, o);
            kss += __shfl_xor_sync(0xffffffffu, kss, o);
        }
        float qinv = 1.0f / fmaxf(sqrtf(qss), 1e-12f);
        float kinv = 1.0f / fmaxf(sqrtf(kss), 1e-12f);
        qs[r * 33 + tx] = qv * qinv;
        ks[r * 33 + tx] = kv * kinv;
        vs[r * 32 + tx] = vv;
    }
    __syncthreads();

    const float scl = fminf(__expf(logit_scale[h]), 100.0f);

    // 3 fused pairs: (0,64) (128,192) (256,320-tail)
    attn_pair<4>(0,   64,  sm, bmb, scl, b, h, ty, tx);
    prefetch_bm<4>(128, ps, bmb, ty, tx);       // next pair's A, hidden under its Phase A
    attn_pair<4>(128, 192, sm, bmb, scl, b, h, ty, tx);
    prefetch_bm<4>(256, ps, bmb, ty, tx);
    attn_pair<2>(256, 320, sm, bmb, scl, b, h, ty, tx);   // tail sub-tile: rows 320..351
}

// ---------------- kernel 4: output projection ----------------
__global__ __launch_bounds__(256, 2) void proj_gemm(const float* __restrict__ W,
                                                    const float* __restrict__ bias,
                                                    float* __restrict__ out) {
    extern __shared__ float sm[];
    float* xs_t = sm;
    float* ws_t = sm + 96 * 132;
    const int tid = threadIdx.x;
    const int m0  = blockIdx.x * 128;

    float acc[8][6];
    gemm_core(g_ao + (size_t)m0 * 96, W, xs_t, ws_t, acc, tid);

    const int tx = tid & 15, ty = tid >> 4;
#pragma unroll
    for (int i = 0; i < 8; i++) {
        int m = m0 + ty * 8 + i;
#pragma unroll
        for (int j = 0; j < 6; j++) {
            int c = tx * 6 + j;
            out[(size_t)m * 96 + c] = acc[i][j] + bias[c];
        }
    }
}

// ---------------- launch ----------------
extern "C" void kernel_launch(void* const* d_in, const int* in_sizes, int n_in,
                              void* d_out, int out_size) {
    const float* x     = (const float*)d_in[0];
    const float* mask  = (const float*)d_in[1];
    const float* Wqkv  = (const float*)d_in[2];
    const float* bqkv  = (const float*)d_in[3];
    const float* Wproj = (const float*)d_in[4];
    const float* bproj = (const float*)d_in[5];
    const float* ls    = (const float*)d_in[6];
    const float* table = (const float*)d_in[7];
    const int*   rpi   = (const int*)d_in[8];
    float* out = (float*)d_out;

    const int smG = (96 * 132 + 96 * 100) * 4;   // 89088 B
    const int smA = SM_FLOATS * 4;               // 222912 B
    cudaFuncSetAttribute(qkv_gemm,  cudaFuncAttributeMaxDynamicSharedMemorySize, smG);
    cudaFuncSetAttribute(proj_gemm, cudaFuncAttributeMaxDynamicSharedMemorySize, smG);
    cudaFuncSetAttribute(attn_kernel, cudaFuncAttributeMaxDynamicSharedMemorySize, smA);

    const size_t bm_total = (size_t)NW_ * HEADS * N_ * PSW;
    bm_kernel<<<(unsigned)((bm_total + 255) / 256), 256>>>(rpi, table, mask);
    qkv_gemm<<<dim3(ROWS_TOT / 128, 3), 256, smG>>>(x, Wqkv, bqkv);
    attn_kernel<<<BW_ * HEADS, 512, smA>>>(ls);
    proj_gemm<<<ROWS_TOT / 128, 256, smG>>>(Wproj, bproj, out);
}